// round 13
// baseline (speedup 1.0000x reference)
#include <cuda_runtime.h>

namespace {

constexpr int H = 4096, W = 4096;
constexpr int ROWS = 8;             // output rows per block
constexpr int WPB  = 4;             // warps per block
constexpr int CPW  = 256;           // cols per warp (32 lanes x 8)
constexpr int CPB  = WPB * CPW;     // 1024 cols per block
constexpr int NT   = WPB * 32;

struct Row { float4 a, b; float2 h; };

__device__ __forceinline__ float Af(float t, float m, float b) {
    return __fadd_rn(__fmaf_rn(2.0f, m, t), b);     // t + 2m + b (2m exact)
}
__device__ __forceinline__ float GyF(float l, float c, float r) {
    return __fadd_rn(__fmaf_rn(2.0f, c, l), r);     // l + 2c + r
}
__device__ __forceinline__ float Sq(float gx, float gy) {
    return __fadd_rn(__fmul_rn(gx, gx), __fmul_rn(gy, gy));
}

// Exact reference chain on squared magnitudes (rare path).
__device__ __forceinline__ float slowNms(float sp, float sc, float sn) {
    float mp = __fsqrt_rn(sp), mc = __fsqrt_rn(sc), mn = __fsqrt_rn(sn);
    float e = ((mc >= mp) && (mc >= mn)) ? mc : 0.0f;
    return (e > 0.15f) ? 255.0f : ((e >= 0.05f) ? 0.0f : e);
}

// Squared-domain fast decision (exact outside slow-flagged cases).
__device__ __forceinline__ float fastNms(float sp, float sc, float sn, bool& slow) {
    float mx = fmaxf(sp, sn);
    bool kept   = (sc >= mx);
    bool keptL  = (__fmul_rn(sc, 1.000001f) >= mx);
    bool strong = (sc > 0.0225001f);
    bool hit = kept && strong;
    slow = keptL && !hit;
    return hit ? 255.0f : 0.0f;
}

template <bool GUARD>
__device__ __forceinline__ void tile(const float* __restrict__ x, float* __restrict__ out) {
    const int lane = threadIdx.x & 31;
    const int warp = threadIdx.x >> 5;
    const int c0 = blockIdx.x * CPB + warp * CPW + lane * 8;
    const int r0 = blockIdx.y * ROWS;

    const bool isL = (lane == 0);
    const bool isR = (lane == 31);
    const int hc = isL ? (c0 - 2) : (c0 + 8);
    const bool hok = (isL || isR) && ((unsigned)hc < (unsigned)W);

    const float* p  = x + (size_t)r0 * W + c0;   // tracks current first output row
    const float* ph = x + (size_t)r0 * W + hc;
    float*       q  = out + (size_t)r0 * W + c0;

    auto ldrow = [&](int dr, int r) -> Row {
        Row v;
        if (!GUARD || (unsigned)r < (unsigned)H) {
            v.a = *reinterpret_cast<const float4*>(p + (ptrdiff_t)dr * W);
            v.b = *reinterpret_cast<const float4*>(p + (ptrdiff_t)dr * W + 4);
        } else {
            v.a = make_float4(0.f, 0.f, 0.f, 0.f);
            v.b = make_float4(0.f, 0.f, 0.f, 0.f);
        }
        if (hok && (!GUARD || (unsigned)r < (unsigned)H))
            v.h = *reinterpret_cast<const float2*>(ph + (ptrdiff_t)dr * W);
        else
            v.h = make_float2(0.f, 0.f);
        return v;
    };

    auto out_row = [&](const Row& T, const Row& M, const Row& Bo, int gr, float* qq) {
        float A0 = Af(T.a.x, M.a.x, Bo.a.x), B0 = __fsub_rn(T.a.x, Bo.a.x);
        float A1 = Af(T.a.y, M.a.y, Bo.a.y), B1 = __fsub_rn(T.a.y, Bo.a.y);
        float A2 = Af(T.a.z, M.a.z, Bo.a.z), B2 = __fsub_rn(T.a.z, Bo.a.z);
        float A3 = Af(T.a.w, M.a.w, Bo.a.w), B3 = __fsub_rn(T.a.w, Bo.a.w);
        float A4 = Af(T.b.x, M.b.x, Bo.b.x), B4 = __fsub_rn(T.b.x, Bo.b.x);
        float A5 = Af(T.b.y, M.b.y, Bo.b.y), B5 = __fsub_rn(T.b.y, Bo.b.y);
        float A6 = Af(T.b.z, M.b.z, Bo.b.z), B6 = __fsub_rn(T.b.z, Bo.b.z);
        float A7 = Af(T.b.w, M.b.w, Bo.b.w), B7 = __fsub_rn(T.b.w, Bo.b.w);
        float hA0 = Af(T.h.x, M.h.x, Bo.h.x), hB0 = __fsub_rn(T.h.x, Bo.h.x);
        float hA1 = Af(T.h.y, M.h.y, Bo.h.y), hB1 = __fsub_rn(T.h.y, Bo.h.y);

        // single round of 8 independent shuffles: +/-1 and +/-2 column context
        float Am1 = __shfl_up_sync(0xffffffffu, A7, 1);
        float Bm1 = __shfl_up_sync(0xffffffffu, B7, 1);
        float Am2 = __shfl_up_sync(0xffffffffu, A6, 1);
        float Bm2 = __shfl_up_sync(0xffffffffu, B6, 1);
        float Ap8 = __shfl_down_sync(0xffffffffu, A0, 1);
        float Bp8 = __shfl_down_sync(0xffffffffu, B0, 1);
        float Ap9 = __shfl_down_sync(0xffffffffu, A1, 1);
        float Bp9 = __shfl_down_sync(0xffffffffu, B1, 1);
        if (isL) { Am1 = hA1; Bm1 = hB1; Am2 = hA0; Bm2 = hB0; }
        if (isR) { Ap8 = hA0; Bp8 = hB0; Ap9 = hA1; Bp9 = hB1; }

        // squared magnitudes (sm1/sp8 bitwise == neighbor lane's s7/s0)
        float sm1 = Sq(__fsub_rn(A0, Am2),  GyF(Bm2, Bm1, B0));
        float s0  = Sq(__fsub_rn(A1, Am1),  GyF(Bm1, B0, B1));
        float s1  = Sq(__fsub_rn(A2, A0),   GyF(B0, B1, B2));
        float s2  = Sq(__fsub_rn(A3, A1),   GyF(B1, B2, B3));
        float s3  = Sq(__fsub_rn(A4, A2),   GyF(B2, B3, B4));
        float s4  = Sq(__fsub_rn(A5, A3),   GyF(B3, B4, B5));
        float s5  = Sq(__fsub_rn(A6, A4),   GyF(B4, B5, B6));
        float s6  = Sq(__fsub_rn(A7, A5),   GyF(B5, B6, B7));
        float s7  = Sq(__fsub_rn(Ap8, A6),  GyF(B6, B7, Bp8));
        float sp8 = Sq(__fsub_rn(Ap9, A7),  GyF(B7, Bp8, Bp9));

        bool w0, w1, w2, w3, w4, w5, w6, w7;
        float o0 = fastNms(sm1, s0, s1, w0);
        float o1 = fastNms(s0,  s1, s2, w1);
        float o2 = fastNms(s1,  s2, s3, w2);
        float o3 = fastNms(s2,  s3, s4, w3);
        float o4 = fastNms(s3,  s4, s5, w4);
        float o5 = fastNms(s4,  s5, s6, w5);
        float o6 = fastNms(s5,  s6, s7, w6);
        float o7 = fastNms(s6,  s7, sp8, w7);

        bool anySlow = w0 | w1 | w2 | w3 | w4 | w5 | w6 | w7;
        if (__any_sync(0xffffffffu, anySlow)) {
            if (w0) o0 = slowNms(sm1, s0, s1);
            if (w1) o1 = slowNms(s0,  s1, s2);
            if (w2) o2 = slowNms(s1,  s2, s3);
            if (w3) o3 = slowNms(s2,  s3, s4);
            if (w4) o4 = slowNms(s3,  s4, s5);
            if (w5) o5 = slowNms(s4,  s5, s6);
            if (w6) o6 = slowNms(s5,  s6, s7);
            if (w7) o7 = slowNms(s6,  s7, sp8);
        }

        if (GUARD && (gr == 0 || gr == H - 1)) {
            o0 = o1 = o2 = o3 = o4 = o5 = o6 = o7 = 0.0f;
        }
        if (c0 == 0) o0 = 0.0f;          // image left border
        if (c0 + 8 == W) o7 = 0.0f;      // image right border

        // streaming stores: output never re-read; keep L2 for input rows
        __stcs(reinterpret_cast<float4*>(qq),     make_float4(o0, o1, o2, o3));
        __stcs(reinterpret_cast<float4*>(qq + 4), make_float4(o4, o5, o6, o7));
    };

    Row ra = ldrow(-1, r0 - 1);
    Row rb = ldrow(0,  r0);
    Row rc = ldrow(1,  r0 + 1);

#pragma unroll 2
    for (int i = 0; i < ROWS; i += 2) {
        const int gr = r0 + i;
        // batch-load the next two rows up front -> doubled MLP + load distance
        Row rd = ldrow(2, gr + 2);
        Row re = ldrow(3, gr + 3);

        out_row(ra, rb, rc, gr,     q);
        out_row(rb, rc, rd, gr + 1, q + W);

        ra = rc; rb = rd; rc = re;
        p += 2 * W; ph += 2 * W; q += 2 * W;
    }
}

__global__ void __launch_bounds__(NT, 7) sobel_canny(const float* __restrict__ x,
                                                     float* __restrict__ out) {
    if (blockIdx.y == 0 || blockIdx.y == gridDim.y - 1)
        tile<true>(x, out);
    else
        tile<false>(x, out);
}

}  // namespace

extern "C" void kernel_launch(void* const* d_in, const int* in_sizes, int n_in,
                              void* d_out, int out_size) {
    const float* x = (const float*)d_in[0];
    float* o = (float*)d_out;
    dim3 grid(W / CPB, H / ROWS);
    sobel_canny<<<grid, NT>>>(x, o);
}

// round 14
// speedup vs baseline: 1.0845x; 1.0845x over previous
#include <cuda_runtime.h>

namespace {

constexpr int H = 4096, W = 4096;
constexpr int ROWS = 16;            // output rows per block -> grid = 1024 CTAs (single wave)
constexpr int WPB  = 4;             // warps per block
constexpr int CPW  = 256;           // cols per warp (32 lanes x 8)
constexpr int CPB  = WPB * CPW;     // 1024 cols per block
constexpr int NT   = WPB * 32;

__device__ __forceinline__ float Af(float t, float m, float b) {
    return __fadd_rn(__fmaf_rn(2.0f, m, t), b);     // t + 2m + b (2m exact)
}
__device__ __forceinline__ float GyF(float l, float c, float r) {
    return __fadd_rn(__fmaf_rn(2.0f, c, l), r);     // l + 2c + r
}
__device__ __forceinline__ float Sq(float gx, float gy) {
    return __fadd_rn(__fmul_rn(gx, gx), __fmul_rn(gy, gy));
}

// Exact reference chain on squared magnitudes (rare path).
__device__ __forceinline__ float slowNms(float sp, float sc, float sn) {
    float mp = __fsqrt_rn(sp), mc = __fsqrt_rn(sc), mn = __fsqrt_rn(sn);
    float e = ((mc >= mp) && (mc >= mn)) ? mc : 0.0f;
    return (e > 0.15f) ? 255.0f : ((e >= 0.05f) ? 0.0f : e);
}

// Squared-domain fast decision (exact outside slow-flagged cases).
__device__ __forceinline__ float fastNms(float sp, float sc, float sn, bool& slow) {
    float mx = fmaxf(sp, sn);
    bool kept   = (sc >= mx);
    bool keptL  = (__fmul_rn(sc, 1.000001f) >= mx);
    bool strong = (sc > 0.0225001f);
    bool hit = kept && strong;
    slow = keptL && !hit;
    return hit ? 255.0f : 0.0f;
}

template <bool GUARD>
__device__ __forceinline__ void tile(const float* __restrict__ x, float* __restrict__ out) {
    const int lane = threadIdx.x & 31;
    const int warp = threadIdx.x >> 5;
    const int c0 = blockIdx.x * CPB + warp * CPW + lane * 8;
    const int r0 = blockIdx.y * ROWS;

    const bool isL = (lane == 0);
    const bool isR = (lane == 31);
    const int hc = isL ? (c0 - 2) : (c0 + 8);
    const bool hok = (isL || isR) && ((unsigned)hc < (unsigned)W);

    const float* p  = x + (size_t)r0 * W + c0;
    const float* ph = x + (size_t)r0 * W + hc;
    float*       q  = out + (size_t)r0 * W + c0;

    auto ld8 = [&](const float* a, int r, float4& u, float4& v) {
        if (!GUARD || (unsigned)r < (unsigned)H) {
            u = *reinterpret_cast<const float4*>(a);
            v = *reinterpret_cast<const float4*>(a + 4);
        } else {
            u = make_float4(0.f, 0.f, 0.f, 0.f);
            v = make_float4(0.f, 0.f, 0.f, 0.f);
        }
    };
    auto ld2 = [&](const float* a, int r) -> float2 {
        if (hok && (!GUARD || (unsigned)r < (unsigned)H))
            return *reinterpret_cast<const float2*>(a);
        return make_float2(0.f, 0.f);
    };

    float4 tA, tB, mA, mB, bA, bB;
    ld8(p - W, r0 - 1, tA, tB);
    ld8(p,     r0,     mA, mB);
    ld8(p + W, r0 + 1, bA, bB);
    float2 ht = ld2(ph - W, r0 - 1), hm = ld2(ph, r0), hb = ld2(ph + W, r0 + 1);

#pragma unroll 4
    for (int i = 0; i < ROWS; i++) {
        const int gr = r0 + i;
        float4 nA, nB;
        ld8(p + 2 * W, gr + 2, nA, nB);          // prefetch row gr+2
        float2 hn = ld2(ph + 2 * W, gr + 2);

        // column sums/diffs
        float A0 = Af(tA.x, mA.x, bA.x), B0 = __fsub_rn(tA.x, bA.x);
        float A1 = Af(tA.y, mA.y, bA.y), B1 = __fsub_rn(tA.y, bA.y);
        float A2 = Af(tA.z, mA.z, bA.z), B2 = __fsub_rn(tA.z, bA.z);
        float A3 = Af(tA.w, mA.w, bA.w), B3 = __fsub_rn(tA.w, bA.w);
        float A4 = Af(tB.x, mB.x, bB.x), B4 = __fsub_rn(tB.x, bB.x);
        float A5 = Af(tB.y, mB.y, bB.y), B5 = __fsub_rn(tB.y, bB.y);
        float A6 = Af(tB.z, mB.z, bB.z), B6 = __fsub_rn(tB.z, bB.z);
        float A7 = Af(tB.w, mB.w, bB.w), B7 = __fsub_rn(tB.w, bB.w);
        float hA0 = Af(ht.x, hm.x, hb.x), hB0 = __fsub_rn(ht.x, hb.x);
        float hA1 = Af(ht.y, hm.y, hb.y), hB1 = __fsub_rn(ht.y, hb.y);

        // single round of 8 independent shuffles: +/-1 and +/-2 column context
        float Am1 = __shfl_up_sync(0xffffffffu, A7, 1);
        float Bm1 = __shfl_up_sync(0xffffffffu, B7, 1);
        float Am2 = __shfl_up_sync(0xffffffffu, A6, 1);
        float Bm2 = __shfl_up_sync(0xffffffffu, B6, 1);
        float Ap8 = __shfl_down_sync(0xffffffffu, A0, 1);
        float Bp8 = __shfl_down_sync(0xffffffffu, B0, 1);
        float Ap9 = __shfl_down_sync(0xffffffffu, A1, 1);
        float Bp9 = __shfl_down_sync(0xffffffffu, B1, 1);
        if (isL) { Am1 = hA1; Bm1 = hB1; Am2 = hA0; Bm2 = hB0; }
        if (isR) { Ap8 = hA0; Bp8 = hB0; Ap9 = hA1; Bp9 = hB1; }

        // squared magnitudes (sm1/sp8 bitwise == neighbor lane's s7/s0)
        float sm1 = Sq(__fsub_rn(A0, Am2),  GyF(Bm2, Bm1, B0));
        float s0  = Sq(__fsub_rn(A1, Am1),  GyF(Bm1, B0, B1));
        float s1  = Sq(__fsub_rn(A2, A0),   GyF(B0, B1, B2));
        float s2  = Sq(__fsub_rn(A3, A1),   GyF(B1, B2, B3));
        float s3  = Sq(__fsub_rn(A4, A2),   GyF(B2, B3, B4));
        float s4  = Sq(__fsub_rn(A5, A3),   GyF(B3, B4, B5));
        float s5  = Sq(__fsub_rn(A6, A4),   GyF(B4, B5, B6));
        float s6  = Sq(__fsub_rn(A7, A5),   GyF(B5, B6, B7));
        float s7  = Sq(__fsub_rn(Ap8, A6),  GyF(B6, B7, Bp8));
        float sp8 = Sq(__fsub_rn(Ap9, A7),  GyF(B7, Bp8, Bp9));

        bool w0, w1, w2, w3, w4, w5, w6, w7;
        float o0 = fastNms(sm1, s0, s1, w0);
        float o1 = fastNms(s0,  s1, s2, w1);
        float o2 = fastNms(s1,  s2, s3, w2);
        float o3 = fastNms(s2,  s3, s4, w3);
        float o4 = fastNms(s3,  s4, s5, w4);
        float o5 = fastNms(s4,  s5, s6, w5);
        float o6 = fastNms(s5,  s6, s7, w6);
        float o7 = fastNms(s6,  s7, sp8, w7);

        bool anySlow = w0 | w1 | w2 | w3 | w4 | w5 | w6 | w7;
        if (__any_sync(0xffffffffu, anySlow)) {
            if (w0) o0 = slowNms(sm1, s0, s1);
            if (w1) o1 = slowNms(s0,  s1, s2);
            if (w2) o2 = slowNms(s1,  s2, s3);
            if (w3) o3 = slowNms(s2,  s3, s4);
            if (w4) o4 = slowNms(s3,  s4, s5);
            if (w5) o5 = slowNms(s4,  s5, s6);
            if (w6) o6 = slowNms(s5,  s6, s7);
            if (w7) o7 = slowNms(s6,  s7, sp8);
        }

        if (GUARD && (gr == 0 || gr == H - 1)) {
            o0 = o1 = o2 = o3 = o4 = o5 = o6 = o7 = 0.0f;
        }
        if (c0 == 0) o0 = 0.0f;          // image left border
        if (c0 + 8 == W) o7 = 0.0f;      // image right border

        // streaming stores: output never re-read; keep L2 for input rows
        __stcs(reinterpret_cast<float4*>(q),     make_float4(o0, o1, o2, o3));
        __stcs(reinterpret_cast<float4*>(q + 4), make_float4(o4, o5, o6, o7));

        p += W; ph += W; q += W;
        tA = mA; tB = mB; mA = bA; mB = bB; bA = nA; bB = nB;
        ht = hm; hm = hb; hb = hn;
    }
}

__global__ void __launch_bounds__(NT, 8) sobel_canny(const float* __restrict__ x,
                                                     float* __restrict__ out) {
    if (blockIdx.y == 0 || blockIdx.y == gridDim.y - 1)
        tile<true>(x, out);
    else
        tile<false>(x, out);
}

}  // namespace

extern "C" void kernel_launch(void* const* d_in, const int* in_sizes, int n_in,
                              void* d_out, int out_size) {
    const float* x = (const float*)d_in[0];
    float* o = (float*)d_out;
    dim3 grid(W / CPB, H / ROWS);   // 4 x 256 = 1024 CTAs -> single resident wave
    sobel_canny<<<grid, NT>>>(x, o);
}